// round 14
// baseline (speedup 1.0000x reference)
#include <cuda_runtime.h>
#include <cstdint>

// LearnableFiltration, all three layers on tensor cores (sm_103 family).
// out[b,i,j] = softplus( relu( relu(H1) @ W2 + b2 ) @ W3 + b3 )
// H1[j,h] = wi*W1[0,h] + wj*W1[1,h] + d_ij*W1[2,h] + b1[h];  B=4,N=1024,H=32.
//
// R14 = R13 + software pipelining: L1 MMAs for tile t+stride issue BEFORE the
// L2 MMAs of tile t (independent work covers both MMA-latency windows); the
// L1->L2 cvt happens after L2 issue when L1 results are long ready. af[] is
// the only loop-carried fragment state.

#define NB    4
#define NN    1024
#define NH    32
#define TPB   128                        // 4 warps / block
#define GRID  592                        // 4 blocks/SM * 148 SMs
#define NWT2  (NB * NN * (NN / 32))      // 131072 warp-tiles of 32 j's

static __device__ __forceinline__ uint32_t to_tf32(float x) {
    uint32_t r;
    asm("cvt.rna.tf32.f32 %0, %1;" : "=r"(r) : "f"(x));
    return r;
}
// {lo, hi} -> bf16x2 (lo = low 16 bits = even-k element)
static __device__ __forceinline__ uint32_t bf16x2(float lo, float hi) {
    uint32_t r;
    asm("cvt.rn.bf16x2.f32 %0, %1, %2;" : "=r"(r) : "f"(hi), "f"(lo));
    return r;
}
// packed bf16 relu
static __device__ __forceinline__ uint32_t relu2(uint32_t v) {
    uint32_t r;
    asm("max.bf16x2 %0, %1, %2;" : "=r"(r) : "r"(v), "r"(0u));
    return r;
}

// layer-1: D = A[16x4] @ B[4x8], tf32, C = 0
static __device__ __forceinline__ void mma_l1(float* d, uint32_t a0, uint32_t a1,
                                              uint32_t b0) {
    asm volatile(
        "mma.sync.aligned.m16n8k4.row.col.f32.tf32.tf32.f32 "
        "{%0,%1,%2,%3}, {%4,%5}, {%6}, {%7,%7,%7,%7};"
        : "=f"(d[0]), "=f"(d[1]), "=f"(d[2]), "=f"(d[3])
        : "r"(a0), "r"(a1), "r"(b0), "f"(0.0f));
}
// bf16 m16n8k16: D += A*B
static __device__ __forceinline__ void mma_acc(float* d, const uint32_t* a,
                                               const uint32_t* b) {
    asm volatile(
        "mma.sync.aligned.m16n8k16.row.col.f32.bf16.bf16.f32 "
        "{%0,%1,%2,%3}, {%4,%5,%6,%7}, {%8,%9}, {%0,%1,%2,%3};"
        : "+f"(d[0]), "+f"(d[1]), "+f"(d[2]), "+f"(d[3])
        : "r"(a[0]), "r"(a[1]), "r"(a[2]), "r"(a[3]), "r"(b[0]), "r"(b[1]));
}
// bf16 m16n8k16: D = A*B + {c0,c1,c0,c1}  (bias as C, fresh dest)
static __device__ __forceinline__ void mma_bias(float* d, const uint32_t* a,
                                                const uint32_t* b,
                                                float c0, float c1) {
    asm volatile(
        "mma.sync.aligned.m16n8k16.row.col.f32.bf16.bf16.f32 "
        "{%0,%1,%2,%3}, {%4,%5,%6,%7}, {%8,%9}, {%10,%11,%10,%11};"
        : "=f"(d[0]), "=f"(d[1]), "=f"(d[2]), "=f"(d[3])
        : "r"(a[0]), "r"(a[1]), "r"(a[2]), "r"(a[3]), "r"(b[0]), "r"(b[1]),
          "f"(c0), "f"(c1));
}

// softplus(x) = max(x,0) + ln2 * lg2(1 + 2^(-|x|*log2e)), MUFU approx
static __device__ __forceinline__ float softplus_fast(float x) {
    float t, l;
    const float nax = -fabsf(x) * 1.442695041f;
    asm("ex2.approx.f32 %0, %1;" : "=f"(t) : "f"(nax));
    asm("lg2.approx.f32 %0, %1;" : "=f"(l) : "f"(t + 1.0f));
    return fmaxf(x, 0.0f) + 0.693147181f * l;
}

__global__ void __launch_bounds__(TPB)
lf_mma14_kernel(const float* __restrict__ weights,
                const float* __restrict__ distances,
                const float* __restrict__ W1,
                const float* __restrict__ b1,
                const float* __restrict__ W2,
                const float* __restrict__ b2,
                const float* __restrict__ W3,
                const float* __restrict__ b3,
                float* __restrict__ out)
{
    __shared__ float  sW[NB * NN];    // all weights (16 KB)
    __shared__ float  sW2[NH * NH];   // W2[h][n] row-major

    const int tid  = threadIdx.x;
    const int wid  = tid >> 5;
    const int lane = tid & 31;
    const int q    = lane & 3;        // quad column (k position)
    const int g    = lane >> 2;       // row / n position

    for (int x = tid; x < (NB * NN) / 4; x += TPB)
        ((float4*)sW)[x] = ((const float4*)weights)[x];
    for (int x = tid; x < (NH * NH) / 4; x += TPB)
        ((float4*)sW2)[x] = ((const float4*)W2)[x];
    __syncthreads();

    // ---- loop-invariant register state ----
    uint32_t b1f[4];                  // layer-1 B-frags (tf32): k=q selects row
#pragma unroll
    for (int nt = 0; nt < 4; nt++) {
        const int h = 8 * nt + g;
        const float bv = (q == 0) ? W1[h]
                       : (q == 1) ? W1[NH + h]
                       : (q == 2) ? W1[2 * NH + h]
                                  : b1[h];
        b1f[nt] = to_tf32(bv);
    }
    uint32_t bf[2][4][2];             // layer-2 B-frags (bf16x2)
#pragma unroll
    for (int kt = 0; kt < 2; kt++)
#pragma unroll
        for (int nt = 0; nt < 4; nt++) {
            const int n = 8 * nt + g;
            bf[kt][nt][0] = bf16x2(sW2[(16 * kt + 2 * q)     * NH + n],
                                   sW2[(16 * kt + 2 * q + 1) * NH + n]);
            bf[kt][nt][1] = bf16x2(sW2[(16 * kt + 2 * q + 8) * NH + n],
                                   sW2[(16 * kt + 2 * q + 9) * NH + n]);
        }
    float bc[8];                      // b2 at D cols n = 8nt + 2q + {0,1}
#pragma unroll
    for (int nt = 0; nt < 4; nt++) {
        bc[2 * nt]     = b2[8 * nt + 2 * q];
        bc[2 * nt + 1] = b2[8 * nt + 2 * q + 1];
    }
    uint32_t bf3[2][2];               // layer-3 B-frags: every column = W3
#pragma unroll
    for (int kt = 0; kt < 2; kt++) {
        bf3[kt][0] = bf16x2(W3[16 * kt + 2 * q],     W3[16 * kt + 2 * q + 1]);
        bf3[kt][1] = bf16x2(W3[16 * kt + 2 * q + 8], W3[16 * kt + 2 * q + 9]);
    }
    const float b3v = b3[0];

    const int gw     = blockIdx.x * 4 + wid;
    const int stride = GRID * 4;

    // ---- stage helpers (lambdas capture smem/lane state) ----
    auto l1_stage = [&](int tt, float e0, float e1, float e2, float e3,
                        float (*h1A)[4], float (*h1B)[4]) {
        const float wi = sW[tt >> 5];
        const unsigned jb = ((unsigned)(tt >> 15) << 10) + ((tt & 31) << 5) + g;
        const float wj0 = sW[jb];
        const float wj1 = sW[jb + 8];
        const float wj2 = sW[jb + 16];
        const float wj3 = sW[jb + 24];
        const uint32_t a0A = __float_as_uint(
            (q == 0) ? wi : (q == 1) ? wj0 : (q == 2) ? e0 : 1.0f);
        const uint32_t a1A = __float_as_uint(
            (q == 0) ? wi : (q == 1) ? wj1 : (q == 2) ? e1 : 1.0f);
        const uint32_t a0B = __float_as_uint(
            (q == 0) ? wi : (q == 1) ? wj2 : (q == 2) ? e2 : 1.0f);
        const uint32_t a1B = __float_as_uint(
            (q == 0) ? wi : (q == 1) ? wj3 : (q == 2) ? e3 : 1.0f);
#pragma unroll
        for (int nt = 0; nt < 4; nt++) {
            mma_l1(h1A[nt], a0A, a1A, b1f[nt]);
            mma_l1(h1B[nt], a0B, a1B, b1f[nt]);
        }
    };
    auto cvt_stage = [&](float (*h1A)[4], float (*h1B)[4],
                         uint32_t (*afA)[4], uint32_t (*afB)[4]) {
#pragma unroll
        for (int kt = 0; kt < 2; kt++) {
            const int n0 = 2 * kt, n1 = 2 * kt + 1;
            afA[kt][0] = relu2(bf16x2(h1A[n0][0], h1A[n0][1]));
            afA[kt][1] = relu2(bf16x2(h1A[n0][2], h1A[n0][3]));
            afA[kt][2] = relu2(bf16x2(h1A[n1][0], h1A[n1][1]));
            afA[kt][3] = relu2(bf16x2(h1A[n1][2], h1A[n1][3]));
            afB[kt][0] = relu2(bf16x2(h1B[n0][0], h1B[n0][1]));
            afB[kt][1] = relu2(bf16x2(h1B[n0][2], h1B[n0][3]));
            afB[kt][2] = relu2(bf16x2(h1B[n1][0], h1B[n1][1]));
            afB[kt][3] = relu2(bf16x2(h1B[n1][2], h1B[n1][3]));
        }
    };

    // ---- pipeline state: af for tile t, distances for tile t+stride ----
    uint32_t afA[2][4], afB[2][4];
    float dn0 = 0.f, dn1 = 0.f, dn2 = 0.f, dn3 = 0.f;

    if (gw < NWT2) {
        // prologue: L1 + cvt for first tile
        const unsigned off = ((unsigned)gw << 5) + g;
        float e0 = __ldcs(distances + off);
        float e1 = __ldcs(distances + off + 8);
        float e2 = __ldcs(distances + off + 16);
        float e3 = __ldcs(distances + off + 24);
        float h1A[4][4], h1B[4][4];
        l1_stage(gw, e0, e1, e2, e3, h1A, h1B);
        cvt_stage(h1A, h1B, afA, afB);
        // prefetch distances for gw + stride
        const int tn = gw + stride;
        if (tn < NWT2) {
            const unsigned offn = ((unsigned)tn << 5) + g;
            dn0 = __ldcs(distances + offn);
            dn1 = __ldcs(distances + offn + 8);
            dn2 = __ldcs(distances + offn + 16);
            dn3 = __ldcs(distances + offn + 24);
        }
    }

    for (int t = gw; t < NWT2; t += stride) {
        const int tn = t + stride;
        const int tc = (tn < NWT2) ? tn : 0;   // clamped (garbage ok, unused)

        // ---- step 1: L1 MMAs for NEXT tile (independent of current) ----
        float h1A[4][4], h1B[4][4];
        l1_stage(tc, dn0, dn1, dn2, dn3, h1A, h1B);

        // ---- step 2: L2 MMAs for CURRENT tile (af ready, zero stall) ----
        float accA[4][4], accB[4][4];
#pragma unroll
        for (int nt = 0; nt < 4; nt++) {
            mma_bias(accA[nt], afA[0], bf[0][nt], bc[2 * nt], bc[2 * nt + 1]);
            mma_bias(accB[nt], afB[0], bf[0][nt], bc[2 * nt], bc[2 * nt + 1]);
        }
#pragma unroll
        for (int nt = 0; nt < 4; nt++) {
            mma_acc(accA[nt], afA[1], bf[1][nt]);
            mma_acc(accB[nt], afB[1], bf[1][nt]);
        }

        // ---- step 3: cvt af for next tile (L1 latency hidden under L2) ----
        cvt_stage(h1A, h1B, afA, afB);

        // ---- step 4: relu(acc) -> bf16 L3 A-frags ----
        uint32_t a3A[2][4], a3B[2][4];
#pragma unroll
        for (int kt = 0; kt < 2; kt++) {
            const int n0 = 2 * kt, n1 = 2 * kt + 1;
            a3A[kt][0] = relu2(bf16x2(accA[n0][0], accA[n0][1]));
            a3A[kt][1] = relu2(bf16x2(accA[n0][2], accA[n0][3]));
            a3A[kt][2] = relu2(bf16x2(accA[n1][0], accA[n1][1]));
            a3A[kt][3] = relu2(bf16x2(accA[n1][2], accA[n1][3]));
            a3B[kt][0] = relu2(bf16x2(accB[n0][0], accB[n0][1]));
            a3B[kt][1] = relu2(bf16x2(accB[n0][2], accB[n0][3]));
            a3B[kt][2] = relu2(bf16x2(accB[n1][0], accB[n1][1]));
            a3B[kt][3] = relu2(bf16x2(accB[n1][2], accB[n1][3]));
        }

        // ---- step 5: L3 MMAs + lane-distributed softplus/store ----
        float oA[4], oB[4];
        mma_bias(oA, a3A[0], bf3[0], b3v, b3v);
        mma_bias(oB, a3B[0], bf3[0], b3v, b3v);
        mma_acc(oA, a3A[1], bf3[1]);
        mma_acc(oB, a3B[1], bf3[1]);

        const float v = (q == 0) ? oA[0]
                      : (q == 1) ? oA[2]
                      : (q == 2) ? oB[0]
                                 : oB[2];
        __stcs(out + ((unsigned)t << 5) + 8 * (unsigned)q + g, softplus_fast(v));

        // ---- step 6: prefetch distances for t + 2*stride ----
        const int t2 = tn + stride;
        dn0 = dn1 = dn2 = dn3 = 0.f;
        if (t2 < NWT2) {
            const unsigned off2 = ((unsigned)t2 << 5) + g;
            dn0 = __ldcs(distances + off2);
            dn1 = __ldcs(distances + off2 + 8);
            dn2 = __ldcs(distances + off2 + 16);
            dn3 = __ldcs(distances + off2 + 24);
        }
    }
}

extern "C" void kernel_launch(void* const* d_in, const int* in_sizes, int n_in,
                              void* d_out, int out_size)
{
    const float* weights   = (const float*)d_in[0];
    const float* distances = (const float*)d_in[1];
    const float* W1        = (const float*)d_in[2];
    const float* b1        = (const float*)d_in[3];
    const float* W2        = (const float*)d_in[4];
    const float* b2        = (const float*)d_in[5];
    const float* W3        = (const float*)d_in[6];
    const float* b3        = (const float*)d_in[7];
    float* out             = (float*)d_out;

    lf_mma14_kernel<<<GRID, TPB>>>(weights, distances, W1, b1, W2, b2, W3, b3, out);
}

// round 16
// speedup vs baseline: 1.0825x; 1.0825x over previous
#include <cuda_runtime.h>
#include <cstdint>

// LearnableFiltration, all three layers on tensor cores (sm_103 family).
// out[b,i,j] = softplus( relu( relu(H1) @ W2 + b2 ) @ W3 + b3 )
// H1[j,h] = wi*W1[0,h] + wj*W1[1,h] + d_ij*W1[2,h] + b1[h];  B=4,N=1024,H=32.
//
// R15 = R13 (best: 51.8us) with relu FUSED into the f32->bf16x2 conversions
// via cvt.rn.relu.bf16x2.f32 — replaces all 32 cvt+max pairs per tile with
// single instructions (-32 alu instr/tile, shorter cvt chains). R14's MMA
// reordering is reverted (HMMAs serialize on the tensor pipe per warp; the
// reorder only added register traffic).

#define NB    4
#define NN    1024
#define NH    32
#define TPB   128                        // 4 warps / block
#define GRID  740                        // 5 blocks/SM * 148 SMs
#define NWT2  (NB * NN * (NN / 32))      // 131072 warp-tiles of 32 j's

static __device__ __forceinline__ uint32_t to_tf32(float x) {
    uint32_t r;
    asm("cvt.rna.tf32.f32 %0, %1;" : "=r"(r) : "f"(x));
    return r;
}
// {lo, hi} -> bf16x2 (lo = low 16 bits = even-k element)
static __device__ __forceinline__ uint32_t bf16x2(float lo, float hi) {
    uint32_t r;
    asm("cvt.rn.bf16x2.f32 %0, %1, %2;" : "=r"(r) : "f"(hi), "f"(lo));
    return r;
}
// fused relu + convert: {relu(lo), relu(hi)} -> bf16x2
static __device__ __forceinline__ uint32_t relu_bf16x2(float lo, float hi) {
    uint32_t r;
    asm("cvt.rn.relu.bf16x2.f32 %0, %1, %2;" : "=r"(r) : "f"(hi), "f"(lo));
    return r;
}

// layer-1: D = A[16x4] @ B[4x8], tf32, C = 0
static __device__ __forceinline__ void mma_l1(float* d, uint32_t a0, uint32_t a1,
                                              uint32_t b0) {
    asm volatile(
        "mma.sync.aligned.m16n8k4.row.col.f32.tf32.tf32.f32 "
        "{%0,%1,%2,%3}, {%4,%5}, {%6}, {%7,%7,%7,%7};"
        : "=f"(d[0]), "=f"(d[1]), "=f"(d[2]), "=f"(d[3])
        : "r"(a0), "r"(a1), "r"(b0), "f"(0.0f));
}
// bf16 m16n8k16: D += A*B
static __device__ __forceinline__ void mma_acc(float* d, const uint32_t* a,
                                               const uint32_t* b) {
    asm volatile(
        "mma.sync.aligned.m16n8k16.row.col.f32.bf16.bf16.f32 "
        "{%0,%1,%2,%3}, {%4,%5,%6,%7}, {%8,%9}, {%0,%1,%2,%3};"
        : "+f"(d[0]), "+f"(d[1]), "+f"(d[2]), "+f"(d[3])
        : "r"(a[0]), "r"(a[1]), "r"(a[2]), "r"(a[3]), "r"(b[0]), "r"(b[1]));
}
// bf16 m16n8k16: D = A*B + {c0,c1,c0,c1}  (bias as C, fresh dest)
static __device__ __forceinline__ void mma_bias(float* d, const uint32_t* a,
                                                const uint32_t* b,
                                                float c0, float c1) {
    asm volatile(
        "mma.sync.aligned.m16n8k16.row.col.f32.bf16.bf16.f32 "
        "{%0,%1,%2,%3}, {%4,%5,%6,%7}, {%8,%9}, {%10,%11,%10,%11};"
        : "=f"(d[0]), "=f"(d[1]), "=f"(d[2]), "=f"(d[3])
        : "r"(a[0]), "r"(a[1]), "r"(a[2]), "r"(a[3]), "r"(b[0]), "r"(b[1]),
          "f"(c0), "f"(c1));
}

// softplus(x) = max(x,0) + ln2 * lg2(1 + 2^(-|x|*log2e)), MUFU approx
static __device__ __forceinline__ float softplus_fast(float x) {
    float t, l;
    const float nax = -fabsf(x) * 1.442695041f;
    asm("ex2.approx.f32 %0, %1;" : "=f"(t) : "f"(nax));
    asm("lg2.approx.f32 %0, %1;" : "=f"(l) : "f"(t + 1.0f));
    return fmaxf(x, 0.0f) + 0.693147181f * l;
}

__global__ void __launch_bounds__(TPB)
lf_mma15_kernel(const float* __restrict__ weights,
                const float* __restrict__ distances,
                const float* __restrict__ W1,
                const float* __restrict__ b1,
                const float* __restrict__ W2,
                const float* __restrict__ b2,
                const float* __restrict__ W3,
                const float* __restrict__ b3,
                float* __restrict__ out)
{
    __shared__ float  sW[NB * NN];    // all weights (16 KB)
    __shared__ float  sW2[NH * NH];   // W2[h][n] row-major

    const int tid  = threadIdx.x;
    const int wid  = tid >> 5;
    const int lane = tid & 31;
    const int q    = lane & 3;        // quad column (k position)
    const int g    = lane >> 2;       // row / n position

    for (int x = tid; x < (NB * NN) / 4; x += TPB)
        ((float4*)sW)[x] = ((const float4*)weights)[x];
    for (int x = tid; x < (NH * NH) / 4; x += TPB)
        ((float4*)sW2)[x] = ((const float4*)W2)[x];
    __syncthreads();

    // ---- loop-invariant register state ----
    // layer-1 B-frags (tf32): col h = 8nt + g, row k = q:
    //   k=0 -> W1[0,h], k=1 -> W1[1,h], k=2 -> W1[2,h], k=3 -> b1[h]
    uint32_t b1f[4];
#pragma unroll
    for (int nt = 0; nt < 4; nt++) {
        const int h = 8 * nt + g;
        const float bv = (q == 0) ? W1[h]
                       : (q == 1) ? W1[NH + h]
                       : (q == 2) ? W1[2 * NH + h]
                                  : b1[h];
        b1f[nt] = to_tf32(bv);
    }
    // layer-2 B-frags (bf16x2): col n = 8nt + g, k pairs {2q,2q+1}+16kt and +8
    uint32_t bf[2][4][2];
#pragma unroll
    for (int kt = 0; kt < 2; kt++)
#pragma unroll
        for (int nt = 0; nt < 4; nt++) {
            const int n = 8 * nt + g;
            bf[kt][nt][0] = bf16x2(sW2[(16 * kt + 2 * q)     * NH + n],
                                   sW2[(16 * kt + 2 * q + 1) * NH + n]);
            bf[kt][nt][1] = bf16x2(sW2[(16 * kt + 2 * q + 8) * NH + n],
                                   sW2[(16 * kt + 2 * q + 9) * NH + n]);
        }
    // layer-2 bias at this thread's D columns: n = 8nt + 2q + {0,1}
    float bc[8];
#pragma unroll
    for (int nt = 0; nt < 4; nt++) {
        bc[2 * nt]     = b2[8 * nt + 2 * q];
        bc[2 * nt + 1] = b2[8 * nt + 2 * q + 1];
    }
    // layer-3 B-frags: EVERY column = W3 (broadcast) -> all D cols = row sum
    uint32_t bf3[2][2];
#pragma unroll
    for (int kt = 0; kt < 2; kt++) {
        bf3[kt][0] = bf16x2(W3[16 * kt + 2 * q],     W3[16 * kt + 2 * q + 1]);
        bf3[kt][1] = bf16x2(W3[16 * kt + 2 * q + 8], W3[16 * kt + 2 * q + 9]);
    }
    const float b3v = b3[0];

    const int gw     = blockIdx.x * 4 + wid;
    const int stride = GRID * 4;

    // prefetch first tile's distances (flat elem offset = t*32 + g)
    float d0 = 0.f, d1 = 0.f, d2 = 0.f, d3 = 0.f;
    if (gw < NWT2) {
        const unsigned off = ((unsigned)gw << 5) + g;
        d0 = __ldcs(distances + off);
        d1 = __ldcs(distances + off + 8);
        d2 = __ldcs(distances + off + 16);
        d3 = __ldcs(distances + off + 24);
    }

    for (int t = gw; t < NWT2; t += stride) {
        const float wi = sW[t >> 5];
        const unsigned jbase = ((unsigned)(t >> 15) << 10) + ((t & 31) << 5) + g;
        const float wj0 = sW[jbase];
        const float wj1 = sW[jbase + 8];
        const float wj2 = sW[jbase + 16];
        const float wj3 = sW[jbase + 24];

        // ---- layer-1 A-frags: raw f32 bits (tf32 RZ), k = q selects ----
        const uint32_t a0A = __float_as_uint(
            (q == 0) ? wi : (q == 1) ? wj0 : (q == 2) ? d0 : 1.0f);
        const uint32_t a1A = __float_as_uint(
            (q == 0) ? wi : (q == 1) ? wj1 : (q == 2) ? d1 : 1.0f);
        const uint32_t a0B = __float_as_uint(
            (q == 0) ? wi : (q == 1) ? wj2 : (q == 2) ? d2 : 1.0f);
        const uint32_t a1B = __float_as_uint(
            (q == 0) ? wi : (q == 1) ? wj3 : (q == 2) ? d3 : 1.0f);

        // ---- layer-1: 8 rank-4 MMAs -> H1 in D layout ----
        float h1A[4][4], h1B[4][4];
#pragma unroll
        for (int nt = 0; nt < 4; nt++) {
            mma_l1(h1A[nt], a0A, a1A, b1f[nt]);
            mma_l1(h1B[nt], a0B, a1B, b1f[nt]);
        }

        // ---- fused relu+cvt: D-frag(nt pair) == A-frag(kt) bit layout ----
        uint32_t afA[2][4], afB[2][4];
#pragma unroll
        for (int kt = 0; kt < 2; kt++) {
            const int n0 = 2 * kt, n1 = 2 * kt + 1;
            afA[kt][0] = relu_bf16x2(h1A[n0][0], h1A[n0][1]);
            afA[kt][1] = relu_bf16x2(h1A[n0][2], h1A[n0][3]);
            afA[kt][2] = relu_bf16x2(h1A[n1][0], h1A[n1][1]);
            afA[kt][3] = relu_bf16x2(h1A[n1][2], h1A[n1][3]);
            afB[kt][0] = relu_bf16x2(h1B[n0][0], h1B[n0][1]);
            afB[kt][1] = relu_bf16x2(h1B[n0][2], h1B[n0][3]);
            afB[kt][2] = relu_bf16x2(h1B[n1][0], h1B[n1][1]);
            afB[kt][3] = relu_bf16x2(h1B[n1][2], h1B[n1][3]);
        }

        // prefetch next tile (hide LDG under MMAs)
        const int tn = t + stride;
        float d0n = 0.f, d1n = 0.f, d2n = 0.f, d3n = 0.f;
        if (tn < NWT2) {
            const unsigned offn = ((unsigned)tn << 5) + g;
            d0n = __ldcs(distances + offn);
            d1n = __ldcs(distances + offn + 8);
            d2n = __ldcs(distances + offn + 16);
            d3n = __ldcs(distances + offn + 24);
        }

        // ---- layer-2: 16 bf16 MMAs; first k-step carries b2 bias ----
        float accA[4][4], accB[4][4];
#pragma unroll
        for (int nt = 0; nt < 4; nt++) {
            mma_bias(accA[nt], afA[0], bf[0][nt], bc[2 * nt], bc[2 * nt + 1]);
            mma_bias(accB[nt], afB[0], bf[0][nt], bc[2 * nt], bc[2 * nt + 1]);
        }
#pragma unroll
        for (int nt = 0; nt < 4; nt++) {
            mma_acc(accA[nt], afA[1], bf[1][nt]);
            mma_acc(accB[nt], afB[1], bf[1][nt]);
        }

        // ---- layer-3 prep: fused relu+cvt -> bf16 A-frags ----
        uint32_t a3A[2][4], a3B[2][4];
#pragma unroll
        for (int kt = 0; kt < 2; kt++) {
            const int n0 = 2 * kt, n1 = 2 * kt + 1;
            a3A[kt][0] = relu_bf16x2(accA[n0][0], accA[n0][1]);
            a3A[kt][1] = relu_bf16x2(accA[n0][2], accA[n0][3]);
            a3A[kt][2] = relu_bf16x2(accA[n1][0], accA[n1][1]);
            a3A[kt][3] = relu_bf16x2(accA[n1][2], accA[n1][3]);
            a3B[kt][0] = relu_bf16x2(accB[n0][0], accB[n0][1]);
            a3B[kt][1] = relu_bf16x2(accB[n0][2], accB[n0][3]);
            a3B[kt][2] = relu_bf16x2(accB[n1][0], accB[n1][1]);
            a3B[kt][3] = relu_bf16x2(accB[n1][2], accB[n1][3]);
        }

        // ---- layer-3: 4 MMAs; b3 in C; all D cols identical = row sum ----
        float oA[4], oB[4];
        mma_bias(oA, a3A[0], bf3[0], b3v, b3v);
        mma_bias(oB, a3B[0], bf3[0], b3v, b3v);
        mma_acc(oA, a3A[1], bf3[1]);
        mma_acc(oB, a3B[1], bf3[1]);

        // ---- epilogue: lane q picks j = g + 8q -> one coalesced store ----
        const float v = (q == 0) ? oA[0]
                      : (q == 1) ? oA[2]
                      : (q == 2) ? oB[0]
                                 : oB[2];
        __stcs(out + ((unsigned)t << 5) + 8 * (unsigned)q + g, softplus_fast(v));

        d0 = d0n; d1 = d1n; d2 = d2n; d3 = d3n;
    }
}

extern "C" void kernel_launch(void* const* d_in, const int* in_sizes, int n_in,
                              void* d_out, int out_size)
{
    const float* weights   = (const float*)d_in[0];
    const float* distances = (const float*)d_in[1];
    const float* W1        = (const float*)d_in[2];
    const float* b1        = (const float*)d_in[3];
    const float* W2        = (const float*)d_in[4];
    const float* b2        = (const float*)d_in[5];
    const float* W3        = (const float*)d_in[6];
    const float* b3        = (const float*)d_in[7];
    float* out             = (float*)d_out;

    lf_mma15_kernel<<<GRID, TPB>>>(weights, distances, W1, b1, W2, b2, W3, b3, out);
}